// round 5
// baseline (speedup 1.0000x reference)
#include <cuda_runtime.h>
#include <cuda_bf16.h>
#include <cstdint>

// Problem constants
#define Bz 2
#define Sz 2048
#define Dz 1024
#define Hz 16
#define HDz 64
#define Mz (Bz*Sz)          // 4096 rows

#define LOG2E 1.44269504088896340736f

// -------------------- scratch (device globals; no allocation) --------------------
__device__ __nv_bfloat16 g_qh[Mz * Dz];
__device__ __nv_bfloat16 g_ql[Mz * Dz];
__device__ __nv_bfloat16 g_kh[Mz * Dz];
__device__ __nv_bfloat16 g_kl[Mz * Dz];
__device__ __nv_bfloat16 g_vth[Mz * Dz];      // V^T per head: [bh][d][s]
__device__ __nv_bfloat16 g_vtl[Mz * Dz];
__device__ __nv_bfloat16 g_cth[Mz * Dz];      // ctx hi/lo
__device__ __nv_bfloat16 g_ctl[Mz * Dz];
__device__ __nv_bfloat16 g_ah[Mz * Dz];       // x splits
__device__ __nv_bfloat16 g_al[Mz * Dz];
__device__ __nv_bfloat16 g_wth[4][Dz * Dz];   // W^T hi (q,k,v,o)
__device__ __nv_bfloat16 g_wtl[4][Dz * Dz];   // W^T lo

// ==================== helpers ====================
__device__ __forceinline__ uint32_t smem_u32(const void* p) {
    uint32_t a;
    asm("{ .reg .u64 t; cvta.to.shared.u64 t, %1; cvt.u32.u64 %0, t; }" : "=r"(a) : "l"(p));
    return a;
}
#define CP_ASYNC16(saddr, gptr) \
    asm volatile("cp.async.cg.shared.global [%0], [%1], 16;" :: "r"(saddr), "l"(gptr) : "memory")
#define CP_COMMIT() asm volatile("cp.async.commit_group;" ::: "memory")
#define CP_WAIT(n)  asm volatile("cp.async.wait_group %0;" :: "n"(n) : "memory")

__device__ __forceinline__ void ldm_x4(uint32_t* r, uint32_t addr) {
    asm volatile("ldmatrix.sync.aligned.m8n8.x4.shared.b16 {%0,%1,%2,%3}, [%4];"
                 : "=r"(r[0]), "=r"(r[1]), "=r"(r[2]), "=r"(r[3]) : "r"(addr));
}
__device__ __forceinline__ void mma_16816(float* c, const uint32_t* a, const uint32_t* b) {
    asm volatile(
        "mma.sync.aligned.m16n8k16.row.col.f32.bf16.bf16.f32 "
        "{%0,%1,%2,%3}, {%4,%5,%6,%7}, {%8,%9}, {%0,%1,%2,%3};"
        : "+f"(c[0]), "+f"(c[1]), "+f"(c[2]), "+f"(c[3])
        : "r"(a[0]), "r"(a[1]), "r"(a[2]), "r"(a[3]), "r"(b[0]), "r"(b[1]));
}
__device__ __forceinline__ float ex2f(float x) {
    float y;
    asm("ex2.approx.f32 %0, %1;" : "=f"(y) : "f"(x));
    return y;
}
// split two floats into packed bf16x2 hi and lo residual
__device__ __forceinline__ void split2(float f0, float f1, uint32_t& hi, uint32_t& lo) {
    __nv_bfloat162 h, l;
    h.x = __float2bfloat16(f0);
    h.y = __float2bfloat16(f1);
    l.x = __float2bfloat16(f0 - __bfloat162float(h.x));
    l.y = __float2bfloat16(f1 - __bfloat162float(h.y));
    hi = *(uint32_t*)&h;
    lo = *(uint32_t*)&l;
}

// ==================== split fp32 -> bf16 hi/lo ====================
__global__ __launch_bounds__(256) void split_bf16(
    const float* __restrict__ in, __nv_bfloat16* __restrict__ hi,
    __nv_bfloat16* __restrict__ lo, int n)
{
    int i = (blockIdx.x * 256 + threadIdx.x) * 4;
    if (i >= n) return;
    float4 v = *(const float4*)(in + i);
    uint32_t h01, l01, h23, l23;
    split2(v.x, v.y, h01, l01);
    split2(v.z, v.w, h23, l23);
    ((uint32_t*)(hi + i))[0] = h01;
    ((uint32_t*)(hi + i))[1] = h23;
    ((uint32_t*)(lo + i))[0] = l01;
    ((uint32_t*)(lo + i))[1] = l23;
}

// ==================== transpose + split all 4 weights ====================
__global__ __launch_bounds__(256) void transpose_split_all(
    const float* __restrict__ W0, const float* __restrict__ W1,
    const float* __restrict__ W2, const float* __restrict__ W3,
    __nv_bfloat16* __restrict__ Th, __nv_bfloat16* __restrict__ Tl)
{
    __shared__ float t[32][33];
    const float* Ws[4] = {W0, W1, W2, W3};
    const float* W = Ws[blockIdx.z];
    __nv_bfloat16* th = Th + (size_t)blockIdx.z * Dz * Dz;
    __nv_bfloat16* tl = Tl + (size_t)blockIdx.z * Dz * Dz;
    int n0 = blockIdx.x * 32, k0 = blockIdx.y * 32;
    int tx = threadIdx.x & 31, ty = threadIdx.x >> 5;
#pragma unroll
    for (int i = ty; i < 32; i += 8)
        t[i][tx] = W[(size_t)(k0 + i) * Dz + n0 + tx];
    __syncthreads();
#pragma unroll
    for (int i = ty; i < 32; i += 8) {
        float v = t[tx][i];
        __nv_bfloat16 h = __float2bfloat16(v);
        __nv_bfloat16 l = __float2bfloat16(v - __bfloat162float(h));
        th[(size_t)(n0 + i) * Dz + k0 + tx] = h;
        tl[(size_t)(n0 + i) * Dz + k0 + tx] = l;
    }
}

// ==================== HMMA bf16x3 GEMM mainloop (shared by both kernels) ====================
#define NKC (Dz / 64)         // 16
#define STAGE_BYTES 65536     // 4 * 16KB

__device__ __forceinline__ void gemm_mainloop(
    uint32_t base, int tid, int wid, int lane,
    const __nv_bfloat16* __restrict__ Ah, const __nv_bfloat16* __restrict__ Al,
    const __nv_bfloat16* __restrict__ Bh, const __nv_bfloat16* __restrict__ Bl,
    int m0, int n0, float acc[4][4][4])
{
    const int lq = lane >> 3;
    const int lr = lane & 7;
    const int wm = wid & 1;
    const int wn = wid >> 1;

    const __nv_bfloat16* srcs[4] = {Ah, Al, Bh, Bl};
    const int row0s[4] = {m0, m0, n0, n0};

    auto load_stage = [&](int buf, int kc) {
        uint32_t sb = base + buf * STAGE_BYTES;
#pragma unroll
        for (int t = 0; t < 4; t++) {
            const __nv_bfloat16* src = srcs[t] + (size_t)row0s[t] * Dz + kc * 64;
            uint32_t dst = sb + t * 16384;
#pragma unroll
            for (int it = 0; it < 4; it++) {
                int idx = tid + it * 256;
                int r = idx >> 3;
                int c = idx & 7;
                CP_ASYNC16(dst + r * 128 + ((c ^ (r & 7)) << 4),
                           src + (size_t)r * Dz + c * 8);
            }
        }
    };

#pragma unroll
    for (int i = 0; i < 4; i++)
#pragma unroll
        for (int j = 0; j < 4; j++)
#pragma unroll
            for (int k = 0; k < 4; k++) acc[i][j][k] = 0.f;

    load_stage(0, 0); CP_COMMIT();
    load_stage(1, 1); CP_COMMIT();
    load_stage(2, 2); CP_COMMIT();

    const int rowA = wm * 64 + lr + (lq & 1) * 8;
    const int chA  = (lq >> 1);
    const int rowB = wn * 32 + lr + (lq >> 1) * 8;
    const int chB  = (lq & 1);

    for (int kc = 0; kc < NKC; kc++) {
        CP_WAIT(2);
        __syncthreads();
        uint32_t sb = base + (kc % 3) * STAGE_BYTES;
        uint32_t sAh = sb, sAl = sb + 16384, sBh = sb + 32768, sBl = sb + 49152;

#pragma unroll
        for (int ks = 0; ks < 4; ks++) {
            uint32_t bh[8], bl[8];
#pragma unroll
            for (int nb = 0; nb < 2; nb++) {
                uint32_t off = (uint32_t)(rowB + nb * 16) * 128 +
                               (uint32_t)(((2 * ks + chB) ^ lr) << 4);
                ldm_x4(&bh[nb * 4], sBh + off);
                ldm_x4(&bl[nb * 4], sBl + off);
            }
#pragma unroll
            for (int mi = 0; mi < 4; mi++) {
                uint32_t off = (uint32_t)(rowA + mi * 16) * 128 +
                               (uint32_t)(((2 * ks + chA) ^ lr) << 4);
                uint32_t ah[4], al[4];
                ldm_x4(ah, sAh + off);
                ldm_x4(al, sAl + off);
#pragma unroll
                for (int ni = 0; ni < 4; ni++) {
                    mma_16816(acc[mi][ni], ah, &bh[ni * 2]);
                    mma_16816(acc[mi][ni], ah, &bl[ni * 2]);
                    mma_16816(acc[mi][ni], al, &bh[ni * 2]);
                }
            }
        }
        __syncthreads();
        if (kc + 3 < NKC) load_stage(kc % 3, kc + 3);
        CP_COMMIT();
    }
}

// ==================== merged QKV GEMM (proj = blockIdx.x >> 3) ====================
__global__ __launch_bounds__(256) void gemm_qkv(
    const __nv_bfloat16* __restrict__ Ah, const __nv_bfloat16* __restrict__ Al,
    const __nv_bfloat16* __restrict__ Wth, const __nv_bfloat16* __restrict__ Wtl,
    const float* __restrict__ bq, const float* __restrict__ bk, const float* __restrict__ bv,
    __nv_bfloat16* __restrict__ qh, __nv_bfloat16* __restrict__ ql,
    __nv_bfloat16* __restrict__ kh, __nv_bfloat16* __restrict__ kl,
    __nv_bfloat16* __restrict__ vth, __nv_bfloat16* __restrict__ vtl)
{
    extern __shared__ char dsm[];
    const int tid = threadIdx.x;
    const int wid = tid >> 5;
    const int lane = tid & 31;
    const int proj = blockIdx.x >> 3;           // 0=q 1=k 2=v
    const int n0 = (blockIdx.x & 7) * 128;
    const int m0 = blockIdx.y * 128;

    uint32_t dynu = smem_u32(dsm);
    uint32_t base = (dynu + 1023) & ~1023u;

    const __nv_bfloat16* Bh = Wth + (size_t)proj * Dz * Dz;
    const __nv_bfloat16* Bl = Wtl + (size_t)proj * Dz * Dz;
    const float* bias = (proj == 0) ? bq : (proj == 1) ? bk : bv;

    float acc[4][4][4];
    gemm_mainloop(base, tid, wid, lane, Ah, Al, Bh, Bl, m0, n0, acc);

    const int wm = wid & 1, wn = wid >> 1;
    const int rbase = m0 + wm * 64 + (lane >> 2);
    const int cbase = n0 + wn * 32 + (lane & 3) * 2;
    const float scale = (proj == 0) ? 0.125f * LOG2E : 1.0f;

#pragma unroll
    for (int mi = 0; mi < 4; mi++) {
#pragma unroll
        for (int ni = 0; ni < 4; ni++) {
            int col = cbase + ni * 8;
            float b0 = bias[col], b1 = bias[col + 1];
            int r0 = rbase + mi * 16;
            float v00 = acc[mi][ni][0] + b0, v01 = acc[mi][ni][1] + b1;
            float v10 = acc[mi][ni][2] + b0, v11 = acc[mi][ni][3] + b1;
            if (proj < 2) {
                __nv_bfloat16* OH = proj == 0 ? qh : kh;
                __nv_bfloat16* OL = proj == 0 ? ql : kl;
                uint32_t h0, l0, h1, l1;
                split2(v00 * scale, v01 * scale, h0, l0);
                split2(v10 * scale, v11 * scale, h1, l1);
                *(uint32_t*)(OH + (size_t)r0 * Dz + col) = h0;
                *(uint32_t*)(OL + (size_t)r0 * Dz + col) = l0;
                *(uint32_t*)(OH + (size_t)(r0 + 8) * Dz + col) = h1;
                *(uint32_t*)(OL + (size_t)(r0 + 8) * Dz + col) = l1;
            } else {
                // vt[((b*16+h)*64 + d)*2048 + s]
                float vs[4] = {v00, v01, v10, v11};
#pragma unroll
                for (int e = 0; e < 4; e++) {
                    int r = r0 + (e >> 1) * 8;
                    int c = col + (e & 1);
                    int bb = r >> 11, s = r & 2047;
                    int hh = c >> 6, d = c & 63;
                    size_t idx = ((size_t)((bb << 4) | hh) * 64 + d) * 2048 + s;
                    __nv_bfloat16 h = __float2bfloat16(vs[e]);
                    vth[idx] = h;
                    vtl[idx] = __float2bfloat16(vs[e] - __bfloat162float(h));
                }
            }
        }
    }
}

// ==================== output projection GEMM (fp32 out) ====================
__global__ __launch_bounds__(256) void gemm_out(
    const __nv_bfloat16* __restrict__ Ah, const __nv_bfloat16* __restrict__ Al,
    const __nv_bfloat16* __restrict__ Bh, const __nv_bfloat16* __restrict__ Bl,
    const float* __restrict__ bias, float* __restrict__ C)
{
    extern __shared__ char dsm[];
    const int tid = threadIdx.x;
    const int wid = tid >> 5;
    const int lane = tid & 31;
    const int n0 = blockIdx.x * 128;
    const int m0 = blockIdx.y * 128;

    uint32_t dynu = smem_u32(dsm);
    uint32_t base = (dynu + 1023) & ~1023u;

    float acc[4][4][4];
    gemm_mainloop(base, tid, wid, lane, Ah, Al, Bh, Bl, m0, n0, acc);

    const int wm = wid & 1, wn = wid >> 1;
    const int rbase = m0 + wm * 64 + (lane >> 2);
    const int cbase = n0 + wn * 32 + (lane & 3) * 2;
#pragma unroll
    for (int mi = 0; mi < 4; mi++) {
#pragma unroll
        for (int ni = 0; ni < 4; ni++) {
            int col = cbase + ni * 8;
            float b0 = bias[col], b1 = bias[col + 1];
            int r0 = rbase + mi * 16;
            float2 a = {acc[mi][ni][0] + b0, acc[mi][ni][1] + b1};
            float2 b = {acc[mi][ni][2] + b0, acc[mi][ni][3] + b1};
            *(float2*)(C + (size_t)r0 * Dz + col) = a;
            *(float2*)(C + (size_t)(r0 + 8) * Dz + col) = b;
        }
    }
}

// ==================== HMMA flash attention (causal), bf16x3 ====================
// BR=64, BC=64, 128 threads (4 warps), 2 CTAs/SM.
// Q pre-scaled by 0.125*log2(e); softmax in exp2 domain.
#define ABR 64
#define ABC 64

__global__ __launch_bounds__(128) void flash_hmma(
    const __nv_bfloat16* __restrict__ qh, const __nv_bfloat16* __restrict__ ql,
    const __nv_bfloat16* __restrict__ kh, const __nv_bfloat16* __restrict__ kl,
    const __nv_bfloat16* __restrict__ vth, const __nv_bfloat16* __restrict__ vtl,
    __nv_bfloat16* __restrict__ ch, __nv_bfloat16* __restrict__ cl)
{
    extern __shared__ char dsm[];
    const int tid = threadIdx.x;
    const int wid = tid >> 5;
    const int lane = tid & 31;
    const int lq = lane >> 3;
    const int lr = lane & 7;
    const int qt = gridDim.x - 1 - blockIdx.x;
    const int bh = blockIdx.y;
    const int b = bh >> 4;
    const int h = bh & 15;
    const int i0 = qt * ABR;

    uint32_t dynu = smem_u32(dsm);
    uint32_t base = (dynu + 1023) & ~1023u;
    uint32_t qb = base;                    // Qh 8KB, Ql 8KB
    uint32_t stg = base + 16384;           // 2 stages x 32KB: Kh|Kl|Vth|Vtl 8KB each

    // ---- load Q tile (64 rows x 64 bf16, hi+lo) ----
    {
        const __nv_bfloat16* qsrc[2] = {qh, ql};
#pragma unroll
        for (int it = 0; it < 8; it++) {
            int idx = tid + it * 128;          // 0..1023
            int t = idx >> 9;
            int rem = idx & 511;
            int r = rem >> 3, c = rem & 7;
            CP_ASYNC16(qb + t * 8192 + r * 128 + ((c ^ (r & 7)) << 4),
                       qsrc[t] + (size_t)(b * Sz + i0 + r) * Dz + h * 64 + c * 8);
        }
    }

    auto load_stage = [&](int buf, int jt) {
        int j0 = jt * ABC;
        uint32_t sb = stg + buf * 32768;
#pragma unroll
        for (int it = 0; it < 16; it++) {
            int idx = tid + it * 128;          // 0..2047
            int arr = idx >> 9;
            int rem = idx & 511;
            int r = rem >> 3, c = rem & 7;
            const __nv_bfloat16* src;
            if (arr == 0)      src = kh  + (size_t)(b * Sz + j0 + r) * Dz + h * 64 + c * 8;
            else if (arr == 1) src = kl  + (size_t)(b * Sz + j0 + r) * Dz + h * 64 + c * 8;
            else if (arr == 2) src = vth + ((size_t)bh * 64 + r) * 2048 + j0 + c * 8;
            else               src = vtl + ((size_t)bh * 64 + r) * 2048 + j0 + c * 8;
            CP_ASYNC16(sb + arr * 8192 + r * 128 + ((c ^ (r & 7)) << 4), src);
        }
    };

    const int njt = qt + 1;
    load_stage(0, 0);
    CP_COMMIT();

    const int rowA = wid * 16 + lr + (lq & 1) * 8;   // Q / P rows (0..63)
    const int chA  = lq >> 1;
    const int rowBb = lr + (lq >> 1) * 8;            // + nb*16
    const int chB  = lq & 1;

    float m0 = -1e30f, m1 = -1e30f, l0 = 0.f, l1 = 0.f;
    float o[8][4];
#pragma unroll
    for (int i = 0; i < 8; i++)
#pragma unroll
        for (int j = 0; j < 4; j++) o[i][j] = 0.f;

    for (int jt = 0; jt < njt; jt++) {
        if (jt + 1 < njt) { load_stage((jt + 1) & 1, jt + 1); CP_COMMIT(); CP_WAIT(1); }
        else CP_WAIT(0);
        __syncthreads();

        uint32_t sb = stg + (jt & 1) * 32768;
        uint32_t sKh = sb, sKl = sb + 8192, sVh = sb + 16384, sVl = sb + 24576;

        // ---- scores = Q K^T (x3 split), log2 domain ----
        float sc[8][4];
#pragma unroll
        for (int i = 0; i < 8; i++)
#pragma unroll
            for (int j = 0; j < 4; j++) sc[i][j] = 0.f;

#pragma unroll
        for (int ks = 0; ks < 4; ks++) {
            uint32_t offA = (uint32_t)rowA * 128 + (uint32_t)(((2 * ks + chA) ^ lr) << 4);
            uint32_t ah[4], al[4];
            ldm_x4(ah, qb + offA);
            ldm_x4(al, qb + 8192 + offA);
            uint32_t kb[16];
#pragma unroll
            for (int nb = 0; nb < 4; nb++) {
                uint32_t off = (uint32_t)(nb * 16 + rowBb) * 128 +
                               (uint32_t)(((2 * ks + chB) ^ lr) << 4);
                ldm_x4(&kb[nb * 4], sKh + off);
            }
#pragma unroll
            for (int nt = 0; nt < 8; nt++) {
                mma_16816(sc[nt], ah, &kb[nt * 2]);
                mma_16816(sc[nt], al, &kb[nt * 2]);
            }
#pragma unroll
            for (int nb = 0; nb < 4; nb++) {
                uint32_t off = (uint32_t)(nb * 16 + rowBb) * 128 +
                               (uint32_t)(((2 * ks + chB) ^ lr) << 4);
                ldm_x4(&kb[nb * 4], sKl + off);
            }
#pragma unroll
            for (int nt = 0; nt < 8; nt++)
                mma_16816(sc[nt], ah, &kb[nt * 2]);
        }

        // ---- causal mask (diagonal tile only) ----
        int j0 = jt * ABC;
        int rg0 = i0 + wid * 16 + (lane >> 2);
        if (j0 + ABC - 1 > i0) {
#pragma unroll
            for (int nt = 0; nt < 8; nt++) {
                int cg = j0 + nt * 8 + (lane & 3) * 2;
                if (cg > rg0)     sc[nt][0] = -1e30f;
                if (cg + 1 > rg0) sc[nt][1] = -1e30f;
                if (cg > rg0 + 8)     sc[nt][2] = -1e30f;
                if (cg + 1 > rg0 + 8) sc[nt][3] = -1e30f;
            }
        }

        // ---- online softmax (exp2 domain) ----
        float mx0 = -1e30f, mx1 = -1e30f;
#pragma unroll
        for (int nt = 0; nt < 8; nt++) {
            mx0 = fmaxf(mx0, fmaxf(sc[nt][0], sc[nt][1]));
            mx1 = fmaxf(mx1, fmaxf(sc[nt][2], sc[nt][3]));
        }
        mx0 = fmaxf(mx0, __shfl_xor_sync(0xffffffffu, mx0, 1));
        mx0 = fmaxf(mx0, __shfl_xor_sync(0xffffffffu, mx0, 2));
        mx1 = fmaxf(mx1, __shfl_xor_sync(0xffffffffu, mx1, 1));
        mx1 = fmaxf(mx1, __shfl_xor_sync(0xffffffffu, mx1, 2));
        float mn0 = fmaxf(m0, mx0), mn1 = fmaxf(m1, mx1);
        float a0 = ex2f(m0 - mn0), a1 = ex2f(m1 - mn1);
        m0 = mn0; m1 = mn1;
        float rs0 = 0.f, rs1 = 0.f;
#pragma unroll
        for (int nt = 0; nt < 8; nt++) {
            sc[nt][0] = ex2f(sc[nt][0] - mn0);
            sc[nt][1] = ex2f(sc[nt][1] - mn0);
            sc[nt][2] = ex2f(sc[nt][2] - mn1);
            sc[nt][3] = ex2f(sc[nt][3] - mn1);
            rs0 += sc[nt][0] + sc[nt][1];
            rs1 += sc[nt][2] + sc[nt][3];
        }
        rs0 += __shfl_xor_sync(0xffffffffu, rs0, 1);
        rs0 += __shfl_xor_sync(0xffffffffu, rs0, 2);
        rs1 += __shfl_xor_sync(0xffffffffu, rs1, 1);
        rs1 += __shfl_xor_sync(0xffffffffu, rs1, 2);
        l0 = l0 * a0 + rs0;
        l1 = l1 * a1 + rs1;
#pragma unroll
        for (int nt = 0; nt < 8; nt++) {
            o[nt][0] *= a0; o[nt][1] *= a0;
            o[nt][2] *= a1; o[nt][3] *= a1;
        }

        // ---- O += P V (x3 split; P fragments from registers) ----
#pragma unroll
        for (int kc = 0; kc < 4; kc++) {
            uint32_t ph[4], pl[4];
            split2(sc[2 * kc][0],     sc[2 * kc][1],     ph[0], pl[0]);
            split2(sc[2 * kc][2],     sc[2 * kc][3],     ph[1], pl[1]);
            split2(sc[2 * kc + 1][0], sc[2 * kc + 1][1], ph[2], pl[2]);
            split2(sc[2 * kc + 1][2], sc[2 * kc + 1][3], ph[3], pl[3]);
            uint32_t vb[16];
#pragma unroll
            for (int nb = 0; nb < 4; nb++) {
                uint32_t off = (uint32_t)(nb * 16 + rowBb) * 128 +
                               (uint32_t)(((2 * kc + chB) ^ lr) << 4);
                ldm_x4(&vb[nb * 4], sVh + off);
            }
#pragma unroll
            for (int nt = 0; nt < 8; nt++) {
                mma_16816(o[nt], ph, &vb[nt * 2]);
                mma_16816(o[nt], pl, &vb[nt * 2]);
            }
#pragma unroll
            for (int nb = 0; nb < 4; nb++) {
                uint32_t off = (uint32_t)(nb * 16 + rowBb) * 128 +
                               (uint32_t)(((2 * kc + chB) ^ lr) << 4);
                ldm_x4(&vb[nb * 4], sVl + off);
            }
#pragma unroll
            for (int nt = 0; nt < 8; nt++)
                mma_16816(o[nt], ph, &vb[nt * 2]);
        }
        __syncthreads();
    }

    // ---- normalize, split, store ctx hi/lo ----
    float inv0 = 1.0f / l0, inv1 = 1.0f / l1;
    size_t grow0 = (size_t)(b * Sz + i0 + wid * 16 + (lane >> 2)) * Dz;
    size_t grow1 = grow0 + 8 * Dz;
    int colb = h * 64 + (lane & 3) * 2;
#pragma unroll
    for (int nt = 0; nt < 8; nt++) {
        int col = colb + nt * 8;
        uint32_t h0, lo0, h1, lo1;
        split2(o[nt][0] * inv0, o[nt][1] * inv0, h0, lo0);
        split2(o[nt][2] * inv1, o[nt][3] * inv1, h1, lo1);
        *(uint32_t*)(ch + grow0 + col) = h0;
        *(uint32_t*)(cl + grow0 + col) = lo0;
        *(uint32_t*)(ch + grow1 + col) = h1;
        *(uint32_t*)(cl + grow1 + col) = lo1;
    }
}

// ==================== launch ====================
extern "C" void kernel_launch(void* const* d_in, const int* in_sizes, int n_in,
                              void* d_out, int out_size)
{
    const float* x  = (const float*)d_in[0];
    const float* Wq = (const float*)d_in[1];
    const float* bq = (const float*)d_in[2];
    const float* Wk = (const float*)d_in[3];
    const float* bk = (const float*)d_in[4];
    const float* Wv = (const float*)d_in[5];
    const float* bv = (const float*)d_in[6];
    const float* Wo = (const float*)d_in[7];
    const float* bo = (const float*)d_in[8];
    float* out = (float*)d_out;

    __nv_bfloat16 *gqh, *gql, *gkh, *gkl, *gvth, *gvtl, *gcth, *gctl, *gah, *gal, *gwth, *gwtl;
    cudaGetSymbolAddress((void**)&gqh,  g_qh);
    cudaGetSymbolAddress((void**)&gql,  g_ql);
    cudaGetSymbolAddress((void**)&gkh,  g_kh);
    cudaGetSymbolAddress((void**)&gkl,  g_kl);
    cudaGetSymbolAddress((void**)&gvth, g_vth);
    cudaGetSymbolAddress((void**)&gvtl, g_vtl);
    cudaGetSymbolAddress((void**)&gcth, g_cth);
    cudaGetSymbolAddress((void**)&gctl, g_ctl);
    cudaGetSymbolAddress((void**)&gah,  g_ah);
    cudaGetSymbolAddress((void**)&gal,  g_al);
    cudaGetSymbolAddress((void**)&gwth, g_wth);
    cudaGetSymbolAddress((void**)&gwtl, g_wtl);

    split_bf16<<<Mz * Dz / 1024, 256>>>(x, gah, gal, Mz * Dz);
    transpose_split_all<<<dim3(32, 32, 4), 256>>>(Wq, Wk, Wv, Wo, gwth, gwtl);

    size_t gsm = 3 * STAGE_BYTES + 1024;
    cudaFuncSetAttribute(gemm_qkv, cudaFuncAttributeMaxDynamicSharedMemorySize, (int)gsm);
    cudaFuncSetAttribute(gemm_out, cudaFuncAttributeMaxDynamicSharedMemorySize, (int)gsm);

    // merged Q,K,V projection (grid.x: 0-7 q, 8-15 k, 16-23 v)
    gemm_qkv<<<dim3(24, Mz / 128), 256, gsm>>>(gah, gal, gwth, gwtl, bq, bk, bv,
                                               gqh, gql, gkh, gkl, gvth, gvtl);

    // attention: BR=64, 4 warps, 2 CTAs/SM
    size_t asm_ = 1024 + 16384 + 2 * 32768;   // 82944
    cudaFuncSetAttribute(flash_hmma, cudaFuncAttributeMaxDynamicSharedMemorySize, (int)asm_);
    flash_hmma<<<dim3(Sz / ABR, Bz * Hz), 128, asm_>>>(gqh, gql, gkh, gkl, gvth, gvtl, gcth, gctl);

    // output projection (fp32 out)
    gemm_out<<<dim3(Dz / 128, Mz / 128), 256, gsm>>>(gcth, gctl,
        gwth + 3 * (size_t)Dz * Dz, gwtl + 3 * (size_t)Dz * Dz, bo, out);
}